// round 5
// baseline (speedup 1.0000x reference)
#include <cuda_runtime.h>
#include <cstdint>
#include <cstddef>

// Problem constants (fixed shapes)
#define DM  1024
#define SQL 2048
#define SKL 2048
#define NB  4

// ---------------------------------------------------------------------------
// Scratch (static __device__ arrays: allocation-free per harness rules)
// ---------------------------------------------------------------------------
static __device__ float g_tq[NB * SQL * DM];                 // proj(q) pre-conv
static __device__ float g_tk[NB * SKL * DM];
static __device__ float g_tv[NB * SKL * DM];
static __device__ float g_q [NB * SQL * DM];                 // post-conv
static __device__ float g_k [NB * SKL * DM];
static __device__ float g_v [NB * SKL * DM];
static __device__ float g_lg[(size_t)NB * SQL * SKL];        // logits / attn
static __device__ float g_cx[NB * SQL * DM];                 // context
static __device__ int   g_maskmode;                          // 0=u8 1=i32 2=f32

// ---------------------------------------------------------------------------
// Mask dtype probe: mask holds only 0/1 values. Inspect first 2048 words.
//   float32 layout-> any word == 0x3F800000 (1.0f)          -> mode 2
//   uint8 layout  -> byte-packs of {0,1}: words like 0x01010001 (>1, not 1.0f)
//                                                            -> mode 0
//   int32 layout  -> words only in {0,1}                     -> mode 1
// ---------------------------------------------------------------------------
__global__ void detect_mask_kernel(const unsigned int* __restrict__ m)
{
    int nf = 0, nbig = 0;
    for (int i = 0; i < 2048; i++) {
        unsigned int w = m[i];
        if (w == 0x3F800000u) nf++;
        else if (w != 0u && w != 1u) nbig++;
    }
    g_maskmode = (nf > 0) ? 2 : ((nbig > 0) ? 0 : 1);
}

// ---------------------------------------------------------------------------
// Packed fp32x2 helpers (Blackwell FFMA2 — only reachable via inline PTX)
// ---------------------------------------------------------------------------
__device__ __forceinline__ unsigned long long pk2(float lo, float hi) {
    unsigned long long r;
    asm("mov.b64 %0, {%1, %2};" : "=l"(r) : "f"(lo), "f"(hi));
    return r;
}
__device__ __forceinline__ void upk2(unsigned long long v, float& lo, float& hi) {
    asm("mov.b64 {%0, %1}, %2;" : "=f"(lo), "=f"(hi) : "l"(v));
}
__device__ __forceinline__ unsigned long long ffma2(unsigned long long a,
                                                    unsigned long long b,
                                                    unsigned long long c) {
    unsigned long long d;
    asm("fma.rn.f32x2 %0, %1, %2, %3;" : "=l"(d) : "l"(a), "l"(b), "l"(c));
    return d;
}

// ---------------------------------------------------------------------------
// SGEMM: C[M,N] = A[M,K] * op(B) (+ epilogue)
//   BT=1 : B is [N,K] row-major (C = A B^T)       -- projections, logits
//   BT=0 : B is [K,N] row-major (C = A B)         -- attn * V
//   EPI=0: none   EPI=1: + bias[N]   EPI=2: *scale, mask -> -1e30
// Tiles: 128x128x16, 256 threads, 8x8 per thread, f32x2-packed accumulators,
// register prefetch of the next K-tile under the FMA block.
// ---------------------------------------------------------------------------
template <int BT, int EPI>
__global__ __launch_bounds__(256, 2)
void gemm128(const float* __restrict__ A, const float* __restrict__ B,
             float* __restrict__ C, int M, int N, int K,
             long long batA, long long batB, long long batC,
             const float* __restrict__ bias,
             const void* __restrict__ maskp, float scale)
{
    __shared__ float As[16][128];
    __shared__ float Bs[16][128];

    const int z = blockIdx.z;
    A += (long long)z * batA;
    B += (long long)z * batB;
    C += (long long)z * batC;

    const int m0 = blockIdx.y * 128;
    const int n0 = blockIdx.x * 128;
    const int tid = threadIdx.x;
    const int tx  = tid & 15;
    const int ty  = tid >> 4;
    const int tx4 = tx * 4;
    const int ty4 = ty * 4;

    unsigned long long acc[4][8];
#pragma unroll
    for (int p = 0; p < 4; p++)
#pragma unroll
        for (int j = 0; j < 8; j++) acc[p][j] = 0ull;

    const int arow = tid >> 1;
    const int ac8  = (tid & 1) * 8;
    const float* aptr = A + (size_t)(m0 + arow) * K + ac8;

    const float* bptr;
    int brow, bc8;
    if (BT) {
        brow = tid >> 1; bc8 = (tid & 1) * 8;
        bptr = B + (size_t)(n0 + brow) * K + bc8;
    } else {
        brow = tid >> 4; bc8 = (tid & 15) * 8;
        bptr = B + (size_t)brow * N + n0 + bc8;
    }

    // Prologue: load tile 0 into registers
    float4 a0v = *(const float4*)(aptr);
    float4 a1v = *(const float4*)(aptr + 4);
    float4 b0v = *(const float4*)(bptr);
    float4 b1v = *(const float4*)(bptr + 4);

    for (int k0 = 0; k0 < K; k0 += 16) {
        __syncthreads();

        As[ac8 + 0][arow] = a0v.x; As[ac8 + 1][arow] = a0v.y;
        As[ac8 + 2][arow] = a0v.z; As[ac8 + 3][arow] = a0v.w;
        As[ac8 + 4][arow] = a1v.x; As[ac8 + 5][arow] = a1v.y;
        As[ac8 + 6][arow] = a1v.z; As[ac8 + 7][arow] = a1v.w;
        if (BT) {
            Bs[bc8 + 0][brow] = b0v.x; Bs[bc8 + 1][brow] = b0v.y;
            Bs[bc8 + 2][brow] = b0v.z; Bs[bc8 + 3][brow] = b0v.w;
            Bs[bc8 + 4][brow] = b1v.x; Bs[bc8 + 5][brow] = b1v.y;
            Bs[bc8 + 6][brow] = b1v.z; Bs[bc8 + 7][brow] = b1v.w;
        } else {
            *(float4*)&Bs[brow][bc8]     = b0v;
            *(float4*)&Bs[brow][bc8 + 4] = b1v;
        }
        __syncthreads();

        // Prefetch next K-tile (overlaps the FMA block)
        if (k0 + 16 < K) {
            aptr += 16;
            if (BT) bptr += 16; else bptr += (size_t)16 * N;
            a0v = *(const float4*)(aptr);
            a1v = *(const float4*)(aptr + 4);
            b0v = *(const float4*)(bptr);
            b1v = *(const float4*)(bptr + 4);
        }

#pragma unroll
        for (int kk = 0; kk < 16; kk++) {
            unsigned long long ap[4];
            ap[0] = *(const unsigned long long*)&As[kk][ty4];
            ap[1] = *(const unsigned long long*)&As[kk][ty4 + 2];
            ap[2] = *(const unsigned long long*)&As[kk][64 + ty4];
            ap[3] = *(const unsigned long long*)&As[kk][64 + ty4 + 2];
            float4 q0 = *(const float4*)&Bs[kk][tx4];
            float4 q1 = *(const float4*)&Bs[kk][64 + tx4];
            unsigned long long bb[8];
            bb[0] = pk2(q0.x, q0.x); bb[1] = pk2(q0.y, q0.y);
            bb[2] = pk2(q0.z, q0.z); bb[3] = pk2(q0.w, q0.w);
            bb[4] = pk2(q1.x, q1.x); bb[5] = pk2(q1.y, q1.y);
            bb[6] = pk2(q1.z, q1.z); bb[7] = pk2(q1.w, q1.w);
#pragma unroll
            for (int p = 0; p < 4; p++)
#pragma unroll
                for (int j = 0; j < 8; j++)
                    acc[p][j] = ffma2(ap[p], bb[j], acc[p][j]);
        }
    }

    // Epilogue
    const int mm = (EPI == 2) ? g_maskmode : 0;
    const unsigned char* m8  = (const unsigned char*)maskp;
    const int*           m32 = (const int*)maskp;
    const float*         mf  = (const float*)maskp;

    int rbase[4];
    rbase[0] = m0 + ty4;      rbase[1] = m0 + ty4 + 2;
    rbase[2] = m0 + 64 + ty4; rbase[3] = m0 + 64 + ty4 + 2;
    int cols[8];
#pragma unroll
    for (int j = 0; j < 8; j++)
        cols[j] = n0 + ((j < 4) ? (tx4 + j) : (64 + tx4 + j - 4));

#pragma unroll
    for (int p = 0; p < 4; p++) {
        const int r0 = rbase[p];
#pragma unroll
        for (int j = 0; j < 8; j++) {
            const int c = cols[j];
            float lo, hi;
            upk2(acc[p][j], lo, hi);
            if (EPI == 1) {
                const float bv = bias[c];
                lo += bv; hi += bv;
            }
            if (EPI == 2) {
                lo *= scale; hi *= scale;
                const size_t i0 = (size_t)r0 * N + c;
                const size_t i1 = i0 + N;
                bool v0, v1;
                if (mm == 0)      { v0 = m8[i0]  != 0;    v1 = m8[i1]  != 0;    }
                else if (mm == 1) { v0 = m32[i0] != 0;    v1 = m32[i1] != 0;    }
                else              { v0 = mf[i0]  != 0.0f; v1 = mf[i1]  != 0.0f; }
                if (!v0) lo = -1.0e30f;
                if (!v1) hi = -1.0e30f;
            }
            C[(size_t)r0 * N + c]       = lo;
            C[(size_t)(r0 + 1) * N + c] = hi;
        }
    }
}

// ---------------------------------------------------------------------------
// Gated depthwise conv along seq (width 3, SAME):  y = x + tanh(g)*(dwconv(x)+cb)
// ---------------------------------------------------------------------------
__global__ void dwconv_gate(const float* __restrict__ X,
                            const float* __restrict__ kern,   // [D,1,3]
                            const float* __restrict__ cb,     // [D]
                            const float* __restrict__ gate,   // scalar
                            float* __restrict__ Y)
{
    const long long i = (long long)blockIdx.x * blockDim.x + threadIdx.x;
    const long long total = (long long)NB * SQL * DM;
    if (i >= total) return;
    const int d = (int)(i % DM);
    const int s = (int)((i / DM) % SQL);
    const float x1 = X[i];
    const float x0 = (s > 0)       ? X[i - DM] : 0.0f;
    const float x2 = (s < SQL - 1) ? X[i + DM] : 0.0f;
    const float y = cb[d] + kern[d * 3 + 0] * x0
                          + kern[d * 3 + 1] * x1
                          + kern[d * 3 + 2] * x2;
    Y[i] = x1 + tanhf(gate[0]) * y;
}

// ---------------------------------------------------------------------------
// Row softmax over 2048 elements, in place. One block (256 thr) per row.
// ---------------------------------------------------------------------------
__global__ void softmax2048(float* __restrict__ L)
{
    float* p = L + (size_t)blockIdx.x * SKL;
    const int t = threadIdx.x;
    const int lane = t & 31, w = t >> 5;
    __shared__ float red[8];

    float v[8];
#pragma unroll
    for (int i = 0; i < 8; i++) v[i] = p[t + 256 * i];

    float m = v[0];
#pragma unroll
    for (int i = 1; i < 8; i++) m = fmaxf(m, v[i]);
#pragma unroll
    for (int o = 16; o > 0; o >>= 1) m = fmaxf(m, __shfl_xor_sync(0xffffffffu, m, o));
    if (lane == 0) red[w] = m;
    __syncthreads();
    if (w == 0) {
        float x = (lane < 8) ? red[lane] : -3.402823466e38f;
#pragma unroll
        for (int o = 4; o > 0; o >>= 1) x = fmaxf(x, __shfl_xor_sync(0xffffffffu, x, o));
        if (lane == 0) red[0] = x;
    }
    __syncthreads();
    m = red[0];
    __syncthreads();

    float s = 0.0f;
#pragma unroll
    for (int i = 0; i < 8; i++) { v[i] = __expf(v[i] - m); s += v[i]; }
#pragma unroll
    for (int o = 16; o > 0; o >>= 1) s += __shfl_xor_sync(0xffffffffu, s, o);
    if (lane == 0) red[w] = s;
    __syncthreads();
    if (w == 0) {
        float x = (lane < 8) ? red[lane] : 0.0f;
#pragma unroll
        for (int o = 4; o > 0; o >>= 1) x += __shfl_xor_sync(0xffffffffu, x, o);
        if (lane == 0) red[0] = x;
    }
    __syncthreads();
    const float inv = 1.0f / red[0];
#pragma unroll
    for (int i = 0; i < 8; i++) p[t + 256 * i] = v[i] * inv;
}

// ---------------------------------------------------------------------------
// Launch
// ---------------------------------------------------------------------------
extern "C" void kernel_launch(void* const* d_in, const int* in_sizes, int n_in,
                              void* d_out, int out_size)
{
    // Resolve input ordering from host-visible sizes.
    // Insertion order: d_in[0] = query_hidden (8388608 elems).
    // Alphabetical:    d_in[0] = attention_mask (4194304 elems).
    int idx_qh, idx_mh, idx_mask, idx_qw, idx_qb, idx_kw, idx_kb, idx_vw, idx_vb,
        idx_ow, idx_ob, idx_qkn, idx_qcb, idx_qg, idx_kkn, idx_kcb, idx_kg,
        idx_vkn, idx_vcb, idx_vg;
    if (in_sizes[0] == SQL * SKL) {
        // alphabetical: attention_mask, k_b, k_cbias, k_gate, k_kernel, k_w,
        // memory_hidden, o_b, o_w, q_b, q_cbias, q_gate, q_kernel, q_w,
        // query_hidden, v_b, v_cbias, v_gate, v_kernel, v_w
        idx_mask = 0;  idx_kb = 1;  idx_kcb = 2;  idx_kg = 3;  idx_kkn = 4;
        idx_kw = 5;    idx_mh = 6;  idx_ob = 7;   idx_ow = 8;  idx_qb = 9;
        idx_qcb = 10;  idx_qg = 11; idx_qkn = 12; idx_qw = 13; idx_qh = 14;
        idx_vb = 15;   idx_vcb = 16; idx_vg = 17; idx_vkn = 18; idx_vw = 19;
    } else {
        idx_qh = 0;  idx_mh = 1;  idx_mask = 2; idx_qw = 3;  idx_qb = 4;
        idx_kw = 5;  idx_kb = 6;  idx_vw = 7;   idx_vb = 8;  idx_ow = 9;
        idx_ob = 10; idx_qkn = 11; idx_qcb = 12; idx_qg = 13;
        idx_kkn = 14; idx_kcb = 15; idx_kg = 16;
        idx_vkn = 17; idx_vcb = 18; idx_vg = 19;
    }

    const float* qh   = (const float*)d_in[idx_qh];
    const float* mh   = (const float*)d_in[idx_mh];
    const void*  msk  = d_in[idx_mask];
    const float* q_w  = (const float*)d_in[idx_qw];
    const float* q_b  = (const float*)d_in[idx_qb];
    const float* k_w  = (const float*)d_in[idx_kw];
    const float* k_b  = (const float*)d_in[idx_kb];
    const float* v_w  = (const float*)d_in[idx_vw];
    const float* v_b  = (const float*)d_in[idx_vb];
    const float* o_w  = (const float*)d_in[idx_ow];
    const float* o_b  = (const float*)d_in[idx_ob];
    const float* q_kn = (const float*)d_in[idx_qkn];
    const float* q_cb = (const float*)d_in[idx_qcb];
    const float* q_g  = (const float*)d_in[idx_qg];
    const float* k_kn = (const float*)d_in[idx_kkn];
    const float* k_cb = (const float*)d_in[idx_kcb];
    const float* k_g  = (const float*)d_in[idx_kg];
    const float* v_kn = (const float*)d_in[idx_vkn];
    const float* v_cb = (const float*)d_in[idx_vcb];
    const float* v_g  = (const float*)d_in[idx_vg];
    float* out = (float*)d_out;

    float *tq, *tk, *tv, *qb, *kb, *vb, *lg, *cx;
    cudaGetSymbolAddress((void**)&tq, g_tq);
    cudaGetSymbolAddress((void**)&tk, g_tk);
    cudaGetSymbolAddress((void**)&tv, g_tv);
    cudaGetSymbolAddress((void**)&qb, g_q);
    cudaGetSymbolAddress((void**)&kb, g_k);
    cudaGetSymbolAddress((void**)&vb, g_v);
    cudaGetSymbolAddress((void**)&lg, g_lg);
    cudaGetSymbolAddress((void**)&cx, g_cx);

    const dim3 thr(256);

    // 0) Mask dtype probe (writes g_maskmode)
    detect_mask_kernel<<<1, 1>>>((const unsigned int*)msk);

    // 1) Projections: X @ W^T + b   (M = B*S = 8192)
    gemm128<1, 1><<<dim3(DM / 128, (NB * SQL) / 128, 1), thr>>>(
        qh, q_w, tq, NB * SQL, DM, DM, 0, 0, 0, q_b, nullptr, 0.f);
    gemm128<1, 1><<<dim3(DM / 128, (NB * SKL) / 128, 1), thr>>>(
        mh, k_w, tk, NB * SKL, DM, DM, 0, 0, 0, k_b, nullptr, 0.f);
    gemm128<1, 1><<<dim3(DM / 128, (NB * SKL) / 128, 1), thr>>>(
        mh, v_w, tv, NB * SKL, DM, DM, 0, 0, 0, v_b, nullptr, 0.f);

    // 2) Gated depthwise conv
    const int total = NB * SQL * DM;
    dwconv_gate<<<total / 256, 256>>>(tq, q_kn, q_cb, q_g, qb);
    dwconv_gate<<<total / 256, 256>>>(tk, k_kn, k_cb, k_g, kb);
    dwconv_gate<<<total / 256, 256>>>(tv, v_kn, v_cb, v_g, vb);

    // 3) Logits: Q K^T / sqrt(D), masked   (per batch)
    gemm128<1, 2><<<dim3(SKL / 128, SQL / 128, NB), thr>>>(
        qb, kb, lg, SQL, SKL, DM,
        (long long)SQL * DM, (long long)SKL * DM, (long long)SQL * SKL,
        nullptr, msk, 0.03125f);

    // 4) Softmax rows
    softmax2048<<<NB * SQL, 256>>>(lg);

    // 5) Context: attn @ V   (per batch, NN)
    gemm128<0, 0><<<dim3(DM / 128, SQL / 128, NB), thr>>>(
        lg, vb, cx, SQL, DM, SKL,
        (long long)SQL * SKL, (long long)SKL * DM, (long long)SQL * DM,
        nullptr, nullptr, 0.f);

    // 6) Output projection: ctx @ o_w^T + o_b  -> d_out
    gemm128<1, 1><<<dim3(DM / 128, (NB * SQL) / 128, 1), thr>>>(
        cx, o_w, out, NB * SQL, DM, DM, 0, 0, 0, o_b, nullptr, 0.f);
}

// round 9
// speedup vs baseline: 1.5283x; 1.5283x over previous
#include <cuda_runtime.h>
#include <cuda_bf16.h>
#include <mma.h>
#include <cstdint>
#include <cstddef>

using namespace nvcuda;

// Problem constants (fixed shapes)
#define DM  1024
#define SQL 2048
#define SKL 2048
#define NB  4

#define NE_X   (NB * SQL * DM)          // 8388608  (activations)
#define NE_W   (DM * DM)                // 1048576  (weights)
#define NE_P   (NB * SQL * SKL)         // 16777216 (attention matrix)

// ---------------------------------------------------------------------------
// Scratch (static __device__ arrays; allocation-free per harness rules)
// ---------------------------------------------------------------------------
static __device__ float g_tq[NE_X];            // proj outputs (pre-conv, fp32)
static __device__ float g_tk[NE_X];
static __device__ float g_tv[NE_X];
static __device__ float g_v [NE_X];            // v post-conv fp32 (pre-transpose)
static __device__ float g_lg[NE_P];            // logits fp32
static __device__ int   g_maskmode;            // 0=u8 1=i32 2=f32

static __device__ __align__(16) __nv_bfloat16 g_qh_h[NE_X], g_qh_l[NE_X];
static __device__ __align__(16) __nv_bfloat16 g_mh_h[NE_X], g_mh_l[NE_X];
static __device__ __align__(16) __nv_bfloat16 g_qw_h[NE_W], g_qw_l[NE_W];
static __device__ __align__(16) __nv_bfloat16 g_kw_h[NE_W], g_kw_l[NE_W];
static __device__ __align__(16) __nv_bfloat16 g_vw_h[NE_W], g_vw_l[NE_W];
static __device__ __align__(16) __nv_bfloat16 g_ow_h[NE_W], g_ow_l[NE_W];
static __device__ __align__(16) __nv_bfloat16 g_q_h [NE_X], g_q_l [NE_X];
static __device__ __align__(16) __nv_bfloat16 g_k_h [NE_X], g_k_l [NE_X];
static __device__ __align__(16) __nv_bfloat16 g_vt_h[NE_X], g_vt_l[NE_X];  // v^T [B,D,S]
static __device__ __align__(16) __nv_bfloat16 g_p_h [NE_P], g_p_l [NE_P];
static __device__ __align__(16) __nv_bfloat16 g_cx_h[NE_X], g_cx_l[NE_X];

__device__ __forceinline__ void split1(float x, __nv_bfloat16& h, __nv_bfloat16& l) {
    h = __float2bfloat16_rn(x);
    l = __float2bfloat16_rn(x - __bfloat162float(h));
}

// ---------------------------------------------------------------------------
// Mask dtype probe (proven in R5)
// ---------------------------------------------------------------------------
__global__ void detect_mask_kernel(const unsigned int* __restrict__ m)
{
    int nf = 0, nbig = 0;
    for (int i = 0; i < 2048; i++) {
        unsigned int w = m[i];
        if (w == 0x3F800000u) nf++;
        else if (w != 0u && w != 1u) nbig++;
    }
    g_maskmode = (nf > 0) ? 2 : ((nbig > 0) ? 0 : 1);
}

// ---------------------------------------------------------------------------
// HMMA (wmma) GEMM: C[M,N] = A·B^T, A=[M,K], B=[N,K], bf16 hi/lo, 3 products.
// EPI=1: +bias fp32 out. EPI=2: *scale + mask -> -1e30, fp32 out.
// EPI=3: split hi/lo bf16 out.
// CTA tile 128x128, K-chunk 64. 8 warps, each 64x32 (4x2 m16n16k16 frags).
// SMEM: 4 bf16 tiles [128][72] (144B rows, conflict-staggered), 73728 B total;
// epilogue staging reuses the same space as float [128][132].
// ---------------------------------------------------------------------------
static constexpr int LDS_T  = 72;                       // bf16 leading dim
static constexpr int TILE_B = 128 * LDS_T * 2;          // 18432 B per tile
static constexpr int SMEM_SZ = 4 * TILE_B;              // 73728 B
static constexpr int LDS_C  = 132;                      // float staging ld

template <int EPI>
__global__ __launch_bounds__(256, 2)
void gemm_wmma(const __nv_bfloat16* __restrict__ Ah, const __nv_bfloat16* __restrict__ Al,
               const __nv_bfloat16* __restrict__ Bh, const __nv_bfloat16* __restrict__ Bl,
               float* __restrict__ C,
               __nv_bfloat16* __restrict__ Ch, __nv_bfloat16* __restrict__ Cl,
               int M, int N, int K,
               long long batA, long long batB, long long batC,
               const float* __restrict__ bias,
               const void* __restrict__ maskp, float scale)
{
    extern __shared__ char smx[];
    __nv_bfloat16* sAh = (__nv_bfloat16*)(smx);
    __nv_bfloat16* sAl = (__nv_bfloat16*)(smx + TILE_B);
    __nv_bfloat16* sBh = (__nv_bfloat16*)(smx + 2 * TILE_B);
    __nv_bfloat16* sBl = (__nv_bfloat16*)(smx + 3 * TILE_B);

    const int tid = threadIdx.x;
    const int wid = tid >> 5;
    const int wm  = wid & 1;      // 0..1 -> 64-row band
    const int wn  = wid >> 1;     // 0..3 -> 32-col band
    const int z = blockIdx.z;

    Ah += (long long)z * batA; Al += (long long)z * batA;
    Bh += (long long)z * batB; Bl += (long long)z * batB;
    if (EPI == 3) { Ch += (long long)z * batC; Cl += (long long)z * batC; }
    else          { C  += (long long)z * batC; }

    const int m0 = blockIdx.y * 128;
    const int n0 = blockIdx.x * 128;

    wmma::fragment<wmma::accumulator, 16, 16, 16, float> acc[4][2];
#pragma unroll
    for (int i = 0; i < 4; i++)
#pragma unroll
        for (int j = 0; j < 2; j++) wmma::fill_fragment(acc[i][j], 0.0f);

    // Loader: thread t copies row r = t>>1, 64B half = t&1 (4 x uint4 / tile)
    const int r = tid >> 1;
    const int half = tid & 1;
    const __nv_bfloat16* pah = Ah + (size_t)(m0 + r) * K + half * 32;
    const __nv_bfloat16* pal = Al + (size_t)(m0 + r) * K + half * 32;
    const __nv_bfloat16* pbh = Bh + (size_t)(n0 + r) * K + half * 32;
    const __nv_bfloat16* pbl = Bl + (size_t)(n0 + r) * K + half * 32;
    const uint32_t dbase = (uint32_t)r * (LDS_T * 2) + half * 64;

    const int NC = K / 64;
    for (int ck = 0; ck < NC; ck++) {
        if (ck > 0) __syncthreads();           // previous compute done
        const size_t o = (size_t)ck * 64;
#pragma unroll
        for (int j = 0; j < 4; j++) {
            const uint32_t d = dbase + j * 16;
            *(uint4*)((char*)sAh + d) = *(const uint4*)(pah + o + j * 8);
            *(uint4*)((char*)sAl + d) = *(const uint4*)(pal + o + j * 8);
            *(uint4*)((char*)sBh + d) = *(const uint4*)(pbh + o + j * 8);
            *(uint4*)((char*)sBl + d) = *(const uint4*)(pbl + o + j * 8);
        }
        __syncthreads();

#pragma unroll
        for (int ks = 0; ks < 4; ks++) {
            const int k0 = ks * 16;
            wmma::fragment<wmma::matrix_a, 16, 16, 16, __nv_bfloat16, wmma::row_major> ah[4], al[4];
#pragma unroll
            for (int i = 0; i < 4; i++) {
                const int ro = (wm * 64 + i * 16) * LDS_T + k0;
                wmma::load_matrix_sync(ah[i], sAh + ro, LDS_T);
                wmma::load_matrix_sync(al[i], sAl + ro, LDS_T);
            }
#pragma unroll
            for (int j = 0; j < 2; j++) {
                wmma::fragment<wmma::matrix_b, 16, 16, 16, __nv_bfloat16, wmma::col_major> bh, bl;
                const int co = (wn * 32 + j * 16) * LDS_T + k0;
                wmma::load_matrix_sync(bh, sBh + co, LDS_T);
                wmma::load_matrix_sync(bl, sBl + co, LDS_T);
#pragma unroll
                for (int i = 0; i < 4; i++) {
                    wmma::mma_sync(acc[i][j], ah[i], bh, acc[i][j]);
                    wmma::mma_sync(acc[i][j], al[i], bh, acc[i][j]);
                    wmma::mma_sync(acc[i][j], ah[i], bl, acc[i][j]);
                }
            }
        }
    }

    // Epilogue: stage accumulators to smem, then coalesced writes
    __syncthreads();
    float* stg = (float*)smx;                  // [128][132]
#pragma unroll
    for (int i = 0; i < 4; i++)
#pragma unroll
        for (int j = 0; j < 2; j++)
            wmma::store_matrix_sync(stg + (wm * 64 + i * 16) * LDS_C + wn * 32 + j * 16,
                                    acc[i][j], LDS_C, wmma::mem_row_major);
    __syncthreads();

    const int mm = (EPI == 2) ? g_maskmode : 0;
    const unsigned char* m8  = (const unsigned char*)maskp;
    const int*           m32 = (const int*)maskp;
    const float*         mf  = (const float*)maskp;

    const int row = tid >> 1;
    const int cb  = (tid & 1) * 64;
    const int gr  = m0 + row;
#pragma unroll
    for (int g = 0; g < 16; g++) {
        const int lc = cb + g * 4;
        const int c  = n0 + lc;
        float v0 = stg[row * LDS_C + lc + 0];
        float v1 = stg[row * LDS_C + lc + 1];
        float v2 = stg[row * LDS_C + lc + 2];
        float v3 = stg[row * LDS_C + lc + 3];
        if (EPI == 1) {
            v0 += bias[c + 0]; v1 += bias[c + 1];
            v2 += bias[c + 2]; v3 += bias[c + 3];
            float4 ov = {v0, v1, v2, v3};
            *(float4*)&C[(size_t)gr * N + c] = ov;
        } else if (EPI == 2) {
            const size_t mi = (size_t)gr * N + c;
            bool b0, b1, b2, b3;
            if (mm == 0) {
                b0 = m8[mi] != 0; b1 = m8[mi + 1] != 0;
                b2 = m8[mi + 2] != 0; b3 = m8[mi + 3] != 0;
            } else if (mm == 1) {
                b0 = m32[mi] != 0; b1 = m32[mi + 1] != 0;
                b2 = m32[mi + 2] != 0; b3 = m32[mi + 3] != 0;
            } else {
                b0 = mf[mi] != 0.f; b1 = mf[mi + 1] != 0.f;
                b2 = mf[mi + 2] != 0.f; b3 = mf[mi + 3] != 0.f;
            }
            float4 ov;
            ov.x = b0 ? v0 * scale : -1.0e30f;
            ov.y = b1 ? v1 * scale : -1.0e30f;
            ov.z = b2 ? v2 * scale : -1.0e30f;
            ov.w = b3 ? v3 * scale : -1.0e30f;
            *(float4*)&C[(size_t)gr * N + c] = ov;
        } else {   // EPI == 3: hi/lo split output
            __nv_bfloat16 h0, l0, h1, l1, h2, l2, h3, l3;
            split1(v0, h0, l0); split1(v1, h1, l1);
            split1(v2, h2, l2); split1(v3, h3, l3);
            const size_t oi = (size_t)gr * N + c;
            *(__nv_bfloat162*)&Ch[oi]     = __nv_bfloat162(h0, h1);
            *(__nv_bfloat162*)&Ch[oi + 2] = __nv_bfloat162(h2, h3);
            *(__nv_bfloat162*)&Cl[oi]     = __nv_bfloat162(l0, l1);
            *(__nv_bfloat162*)&Cl[oi + 2] = __nv_bfloat162(l2, l3);
        }
    }
}

// ---------------------------------------------------------------------------
// Elementwise kernels
// ---------------------------------------------------------------------------
__global__ void split_fp32(const float* __restrict__ x,
                           __nv_bfloat16* __restrict__ h,
                           __nv_bfloat16* __restrict__ l, int n4)
{
    const int i = blockIdx.x * 256 + threadIdx.x;
    if (i >= n4) return;
    float4 v = ((const float4*)x)[i];
    __nv_bfloat16 h0, l0, h1, l1, h2, l2, h3, l3;
    split1(v.x, h0, l0); split1(v.y, h1, l1);
    split1(v.z, h2, l2); split1(v.w, h3, l3);
    ((__nv_bfloat162*)h)[i * 2]     = __nv_bfloat162(h0, h1);
    ((__nv_bfloat162*)h)[i * 2 + 1] = __nv_bfloat162(h2, h3);
    ((__nv_bfloat162*)l)[i * 2]     = __nv_bfloat162(l0, l1);
    ((__nv_bfloat162*)l)[i * 2 + 1] = __nv_bfloat162(l2, l3);
}

__device__ __forceinline__ float conv_val(const float* __restrict__ X, long long i,
                                          int d, int s,
                                          const float* __restrict__ kern,
                                          const float* __restrict__ cb,
                                          const float* __restrict__ gate)
{
    const float x1 = X[i];
    const float x0 = (s > 0)       ? X[i - DM] : 0.0f;
    const float x2 = (s < SQL - 1) ? X[i + DM] : 0.0f;
    const float y = cb[d] + kern[d * 3 + 0] * x0
                          + kern[d * 3 + 1] * x1
                          + kern[d * 3 + 2] * x2;
    return x1 + tanhf(gate[0]) * y;
}

__global__ void dwconv_split(const float* __restrict__ X,
                             const float* __restrict__ kern,
                             const float* __restrict__ cb,
                             const float* __restrict__ gate,
                             __nv_bfloat16* __restrict__ Yh,
                             __nv_bfloat16* __restrict__ Yl)
{
    const long long i = (long long)blockIdx.x * blockDim.x + threadIdx.x;
    if (i >= (long long)NE_X) return;
    const int d = (int)(i % DM);
    const int s = (int)((i / DM) % SQL);
    float v = conv_val(X, i, d, s, kern, cb, gate);
    __nv_bfloat16 h, l;
    split1(v, h, l);
    Yh[i] = h; Yl[i] = l;
}

__global__ void dwconv_plain(const float* __restrict__ X,
                             const float* __restrict__ kern,
                             const float* __restrict__ cb,
                             const float* __restrict__ gate,
                             float* __restrict__ Y)
{
    const long long i = (long long)blockIdx.x * blockDim.x + threadIdx.x;
    if (i >= (long long)NE_X) return;
    const int d = (int)(i % DM);
    const int s = (int)((i / DM) % SQL);
    Y[i] = conv_val(X, i, d, s, kern, cb, gate);
}

// V [B,S,D] fp32 -> V^T [B,D,S] bf16 hi/lo (32x32 smem tiles)
__global__ void transpose_split(const float* __restrict__ V,
                                __nv_bfloat16* __restrict__ Th,
                                __nv_bfloat16* __restrict__ Tl)
{
    __shared__ float tile[32][33];
    const int z = blockIdx.z;
    const float* v = V + (size_t)z * SKL * DM;
    __nv_bfloat16* th = Th + (size_t)z * DM * SKL;
    __nv_bfloat16* tl = Tl + (size_t)z * DM * SKL;
    const int d0 = blockIdx.x * 32;
    const int s0 = blockIdx.y * 32;
    const int tx = threadIdx.x, ty = threadIdx.y;
#pragma unroll
    for (int i = 0; i < 4; i++)
        tile[ty + i * 8][tx] = v[(size_t)(s0 + ty + i * 8) * DM + d0 + tx];
    __syncthreads();
#pragma unroll
    for (int i = 0; i < 4; i++) {
        const float x = tile[tx][ty + i * 8];
        __nv_bfloat16 h, l;
        split1(x, h, l);
        const size_t o = (size_t)(d0 + ty + i * 8) * SKL + s0 + tx;
        th[o] = h; tl[o] = l;
    }
}

// Row softmax over 2048, writes bf16 hi/lo split of probabilities
__global__ void softmax_split(const float* __restrict__ L,
                              __nv_bfloat16* __restrict__ Ph,
                              __nv_bfloat16* __restrict__ Pl)
{
    const float* p = L + (size_t)blockIdx.x * SKL;
    __nv_bfloat16* ph = Ph + (size_t)blockIdx.x * SKL;
    __nv_bfloat16* pl = Pl + (size_t)blockIdx.x * SKL;
    const int t = threadIdx.x;
    const int lane = t & 31, w = t >> 5;
    __shared__ float red[8];

    float v[8];
#pragma unroll
    for (int i = 0; i < 8; i++) v[i] = p[t + 256 * i];

    float m = v[0];
#pragma unroll
    for (int i = 1; i < 8; i++) m = fmaxf(m, v[i]);
#pragma unroll
    for (int o = 16; o > 0; o >>= 1) m = fmaxf(m, __shfl_xor_sync(0xffffffffu, m, o));
    if (lane == 0) red[w] = m;
    __syncthreads();
    if (w == 0) {
        float x = (lane < 8) ? red[lane] : -3.402823466e38f;
#pragma unroll
        for (int o = 4; o > 0; o >>= 1) x = fmaxf(x, __shfl_xor_sync(0xffffffffu, x, o));
        if (lane == 0) red[0] = x;
    }
    __syncthreads();
    m = red[0];
    __syncthreads();

    float s = 0.0f;
#pragma unroll
    for (int i = 0; i < 8; i++) { v[i] = __expf(v[i] - m); s += v[i]; }
#pragma unroll
    for (int o = 16; o > 0; o >>= 1) s += __shfl_xor_sync(0xffffffffu, s, o);
    if (lane == 0) red[w] = s;
    __syncthreads();
    if (w == 0) {
        float x = (lane < 8) ? red[lane] : 0.0f;
#pragma unroll
        for (int o = 4; o > 0; o >>= 1) x += __shfl_xor_sync(0xffffffffu, x, o);
        if (lane == 0) red[0] = x;
    }
    __syncthreads();
    const float inv = 1.0f / red[0];
#pragma unroll
    for (int i = 0; i < 8; i++) {
        __nv_bfloat16 h, l;
        split1(v[i] * inv, h, l);
        ph[t + 256 * i] = h;
        pl[t + 256 * i] = l;
    }
}

// ---------------------------------------------------------------------------
// Launch
// ---------------------------------------------------------------------------
extern "C" void kernel_launch(void* const* d_in, const int* in_sizes, int n_in,
                              void* d_out, int out_size)
{
    // Resolve input ordering (proven in R5)
    int idx_qh, idx_mh, idx_mask, idx_qw, idx_qb, idx_kw, idx_kb, idx_vw, idx_vb,
        idx_ow, idx_ob, idx_qkn, idx_qcb, idx_qg, idx_kkn, idx_kcb, idx_kg,
        idx_vkn, idx_vcb, idx_vg;
    if (in_sizes[0] == SQL * SKL) {
        idx_mask = 0;  idx_kb = 1;  idx_kcb = 2;  idx_kg = 3;  idx_kkn = 4;
        idx_kw = 5;    idx_mh = 6;  idx_ob = 7;   idx_ow = 8;  idx_qb = 9;
        idx_qcb = 10;  idx_qg = 11; idx_qkn = 12; idx_qw = 13; idx_qh = 14;
        idx_vb = 15;   idx_vcb = 16; idx_vg = 17; idx_vkn = 18; idx_vw = 19;
    } else {
        idx_qh = 0;  idx_mh = 1;  idx_mask = 2; idx_qw = 3;  idx_qb = 4;
        idx_kw = 5;  idx_kb = 6;  idx_vw = 7;   idx_vb = 8;  idx_ow = 9;
        idx_ob = 10; idx_qkn = 11; idx_qcb = 12; idx_qg = 13;
        idx_kkn = 14; idx_kcb = 15; idx_kg = 16;
        idx_vkn = 17; idx_vcb = 18; idx_vg = 19;
    }

    const float* qh   = (const float*)d_in[idx_qh];
    const float* mh   = (const float*)d_in[idx_mh];
    const void*  msk  = d_in[idx_mask];
    const float* q_w  = (const float*)d_in[idx_qw];
    const float* q_b  = (const float*)d_in[idx_qb];
    const float* k_w  = (const float*)d_in[idx_kw];
    const float* k_b  = (const float*)d_in[idx_kb];
    const float* v_w  = (const float*)d_in[idx_vw];
    const float* v_b  = (const float*)d_in[idx_vb];
    const float* o_w  = (const float*)d_in[idx_ow];
    const float* o_b  = (const float*)d_in[idx_ob];
    const float* q_kn = (const float*)d_in[idx_qkn];
    const float* q_cb = (const float*)d_in[idx_qcb];
    const float* q_g  = (const float*)d_in[idx_qg];
    const float* k_kn = (const float*)d_in[idx_kkn];
    const float* k_cb = (const float*)d_in[idx_kcb];
    const float* k_g  = (const float*)d_in[idx_kg];
    const float* v_kn = (const float*)d_in[idx_vkn];
    const float* v_cb = (const float*)d_in[idx_vcb];
    const float* v_g  = (const float*)d_in[idx_vg];
    float* out = (float*)d_out;

    // Scratch addresses
    float *tq, *tk, *tv, *vv, *lg;
    cudaGetSymbolAddress((void**)&tq, g_tq);
    cudaGetSymbolAddress((void**)&tk, g_tk);
    cudaGetSymbolAddress((void**)&tv, g_tv);
    cudaGetSymbolAddress((void**)&vv, g_v);
    cudaGetSymbolAddress((void**)&lg, g_lg);
    __nv_bfloat16 *qhh, *qhl, *mhh, *mhl, *qwh, *qwl, *kwh, *kwl, *vwh, *vwl,
                  *owh, *owl, *qH, *qL, *kH, *kL, *vtH, *vtL, *pH, *pL, *cxH, *cxL;
    cudaGetSymbolAddress((void**)&qhh, g_qh_h); cudaGetSymbolAddress((void**)&qhl, g_qh_l);
    cudaGetSymbolAddress((void**)&mhh, g_mh_h); cudaGetSymbolAddress((void**)&mhl, g_mh_l);
    cudaGetSymbolAddress((void**)&qwh, g_qw_h); cudaGetSymbolAddress((void**)&qwl, g_qw_l);
    cudaGetSymbolAddress((void**)&kwh, g_kw_h); cudaGetSymbolAddress((void**)&kwl, g_kw_l);
    cudaGetSymbolAddress((void**)&vwh, g_vw_h); cudaGetSymbolAddress((void**)&vwl, g_vw_l);
    cudaGetSymbolAddress((void**)&owh, g_ow_h); cudaGetSymbolAddress((void**)&owl, g_ow_l);
    cudaGetSymbolAddress((void**)&qH,  g_q_h);  cudaGetSymbolAddress((void**)&qL,  g_q_l);
    cudaGetSymbolAddress((void**)&kH,  g_k_h);  cudaGetSymbolAddress((void**)&kL,  g_k_l);
    cudaGetSymbolAddress((void**)&vtH, g_vt_h); cudaGetSymbolAddress((void**)&vtL, g_vt_l);
    cudaGetSymbolAddress((void**)&pH,  g_p_h);  cudaGetSymbolAddress((void**)&pL,  g_p_l);
    cudaGetSymbolAddress((void**)&cxH, g_cx_h); cudaGetSymbolAddress((void**)&cxL, g_cx_l);

    cudaFuncSetAttribute(gemm_wmma<1>, cudaFuncAttributeMaxDynamicSharedMemorySize, SMEM_SZ);
    cudaFuncSetAttribute(gemm_wmma<2>, cudaFuncAttributeMaxDynamicSharedMemorySize, SMEM_SZ);
    cudaFuncSetAttribute(gemm_wmma<3>, cudaFuncAttributeMaxDynamicSharedMemorySize, SMEM_SZ);

    // 0) Mask dtype probe
    detect_mask_kernel<<<1, 1>>>((const unsigned int*)msk);

    // 1) Split inputs + weights to bf16 hi/lo
    split_fp32<<<NE_X / 1024, 256>>>(qh, qhh, qhl, NE_X / 4);
    split_fp32<<<NE_X / 1024, 256>>>(mh, mhh, mhl, NE_X / 4);
    split_fp32<<<NE_W / 1024, 256>>>(q_w, qwh, qwl, NE_W / 4);
    split_fp32<<<NE_W / 1024, 256>>>(k_w, kwh, kwl, NE_W / 4);
    split_fp32<<<NE_W / 1024, 256>>>(v_w, vwh, vwl, NE_W / 4);
    split_fp32<<<NE_W / 1024, 256>>>(o_w, owh, owl, NE_W / 4);

    // 2) Projections (M=8192, N=1024, K=1024) + bias -> fp32
    gemm_wmma<1><<<dim3(8, 64, 1), 256, SMEM_SZ>>>(
        qhh, qhl, qwh, qwl, tq, nullptr, nullptr,
        8192, 1024, 1024, 0, 0, 0, q_b, nullptr, 0.f);
    gemm_wmma<1><<<dim3(8, 64, 1), 256, SMEM_SZ>>>(
        mhh, mhl, kwh, kwl, tk, nullptr, nullptr,
        8192, 1024, 1024, 0, 0, 0, k_b, nullptr, 0.f);
    gemm_wmma<1><<<dim3(8, 64, 1), 256, SMEM_SZ>>>(
        mhh, mhl, vwh, vwl, tv, nullptr, nullptr,
        8192, 1024, 1024, 0, 0, 0, v_b, nullptr, 0.f);

    // 3) Gated depthwise conv (+split for q,k; plain fp32 for v) + V transpose
    dwconv_split<<<NE_X / 256, 256>>>(tq, q_kn, q_cb, q_g, qH, qL);
    dwconv_split<<<NE_X / 256, 256>>>(tk, k_kn, k_cb, k_g, kH, kL);
    dwconv_plain<<<NE_X / 256, 256>>>(tv, v_kn, v_cb, v_g, vv);
    transpose_split<<<dim3(DM / 32, SKL / 32, NB), dim3(32, 8)>>>(vv, vtH, vtL);

    // 4) Logits: Q K^T / 32, masked  (per batch)
    gemm_wmma<2><<<dim3(16, 16, NB), 256, SMEM_SZ>>>(
        qH, qL, kH, kL, lg, nullptr, nullptr,
        SQL, SKL, DM,
        (long long)SQL * DM, (long long)SKL * DM, (long long)SQL * SKL,
        nullptr, msk, 0.03125f);

    // 5) Softmax + split
    softmax_split<<<NB * SQL, 256>>>(lg, pH, pL);

    // 6) Context: P @ V  via  P[M=SQ,K=SK] x V^T[N=D,K=SK], split output
    gemm_wmma<3><<<dim3(8, 16, NB), 256, SMEM_SZ>>>(
        pH, pL, vtH, vtL, nullptr, cxH, cxL,
        SQL, DM, SKL,
        (long long)SQL * SKL, (long long)DM * SKL, (long long)SQL * DM,
        nullptr, nullptr, 0.f);

    // 7) Output projection + bias -> d_out
    gemm_wmma<1><<<dim3(8, 64, 1), 256, SMEM_SZ>>>(
        cxH, cxL, owh, owl, out, nullptr, nullptr,
        8192, 1024, 1024, 0, 0, 0, o_b, nullptr, 0.f);
}